// round 6
// baseline (speedup 1.0000x reference)
#include <cuda_runtime.h>
#include <cuda_bf16.h>
#include <cuda_fp16.h>

// Problem constants (B=8, N=256, H=128)
#define BB 8
#define NN 256
#define HH 128
#define ROWS (BB * NN)        // 2048
#define TI 32                 // i-rows per edge CTA
#define TJ 32                 // j-tile per edge CTA
#define NSPLIT 8              // j-range split (inner range == TJ)

typedef unsigned long long ull;

// Scratch (allocation-free rule: __device__ globals)
// g_P = 0.5*(node@We1a + be1); g_Q = 0.5*(node@We1b)  (pre-halved for tanh-silu)
__device__ float g_P[ROWS * HH];
__device__ float g_Q[ROWS * HH];
__device__ float g_S[NSPLIT][ROWS * HH];

// ---------------- packed f32x2 + MUFU helpers ----------------
__device__ __forceinline__ ull fma2(ull a, ull b, ull c) {
    ull d; asm("fma.rn.f32x2 %0, %1, %2, %3;" : "=l"(d) : "l"(a), "l"(b), "l"(c)); return d;
}
__device__ __forceinline__ ull add2(ull a, ull b) {
    ull d; asm("add.rn.f32x2 %0, %1, %2;" : "=l"(d) : "l"(a), "l"(b)); return d;
}
__device__ __forceinline__ ull mul2(ull a, ull b) {
    ull d; asm("mul.rn.f32x2 %0, %1, %2;" : "=l"(d) : "l"(a), "l"(b)); return d;
}
__device__ __forceinline__ ull pack2(float lo, float hi) {
    ull d; asm("mov.b64 %0, {%1, %2};" : "=l"(d) : "f"(lo), "f"(hi)); return d;
}
__device__ __forceinline__ void unpack2(ull v, float& lo, float& hi) {
    asm("mov.b64 {%0, %1}, %2;" : "=f"(lo), "=f"(hi) : "l"(v));
}
__device__ __forceinline__ float sqrtfast(float x) {
    float y; asm("sqrt.approx.f32 %0, %1;" : "=f"(y) : "f"(x)); return y;
}
__device__ __forceinline__ float fast_sigmoid(float x) {
    float e; asm("ex2.approx.f32 %0, %1;" : "=f"(e) : "f"(-1.4426950408889634f * x));
    float r; asm("rcp.approx.f32 %0, %1;" : "=f"(r) : "f"(1.0f + e));
    return r;
}
// tanh of both lanes via one MUFU.TANH on f16x2 (t in fp16; product stays fp32)
__device__ __forceinline__ ull tanh2_f16(ull h2) {
    float hl, hh; unpack2(h2, hl, hh);
    __half2 hx = __floats2half2_rn(hl, hh);
    unsigned hb = *reinterpret_cast<unsigned*>(&hx);
    asm("tanh.approx.f16x2 %0, %0;" : "+r"(hb));
    __half2 tx = *reinterpret_cast<__half2*>(&hb);
    float2 tf = __half22float2(tx);
    return pack2(tf.x, tf.y);
}

// ---------------------------------------------------------------------------
// Kernel 1: P' = 0.5*(node@We1a + be1) ; Q' = 0.5*(node@We1b)
// 16 rows/CTA, 512 threads, grid 128 = single wave.
// Row-pairs packed in smem; all math as fma.rn.f32x2 (halved issue count).
// tid bits: [0:7)=k, bit7=half(P/Q), bit8=row-pair-group (4 pairs each).
// ---------------------------------------------------------------------------
__global__ __launch_bounds__(512, 1)
void k_pq(const float* __restrict__ node,
          const float* __restrict__ We1,
          const float* __restrict__ be1) {
    __shared__ __align__(16) ull xs2[HH][8];   // xs2[e][rp] = (x[2rp][e], x[2rp+1][e])
    int row0 = blockIdx.x * 16;
    int tid = threadIdx.x;
    int k = tid & 127;
    int half = (tid >> 7) & 1;
    int rp0 = (tid >> 8) * 4;

    {
        int rp = tid >> 6;            // 0..7
        int e0 = (tid & 63) * 2;      // 0..126
        float2 a = *(const float2*)&node[(row0 + 2 * rp) * HH + e0];
        float2 b = *(const float2*)&node[(row0 + 2 * rp + 1) * HH + e0];
        xs2[e0][rp] = pack2(a.x, b.x);
        xs2[e0 + 1][rp] = pack2(a.y, b.y);
    }
    __syncthreads();

    const float* W = We1 + half * HH * HH + k;
    float bv = half ? 0.0f : be1[k];
    ull acc2[4];
#pragma unroll
    for (int p = 0; p < 4; p++) acc2[p] = pack2(bv, bv);

    ull w0[16], w1[16];
#pragma unroll
    for (int e = 0; e < 16; e++) { float w = W[e * HH]; w0[e] = pack2(w, w); }

#pragma unroll
    for (int c = 0; c < 8; c++) {
        ull* wc = (c & 1) ? w1 : w0;
        ull* wn = (c & 1) ? w0 : w1;
        if (c < 7) {
#pragma unroll
            for (int e = 0; e < 16; e++) {
                float w = W[((c + 1) * 16 + e) * HH];
                wn[e] = pack2(w, w);
            }
        }
#pragma unroll
        for (int e = 0; e < 16; e++) {
            ulonglong2 xa = *(const ulonglong2*)&xs2[c * 16 + e][rp0];
            ulonglong2 xb = *(const ulonglong2*)&xs2[c * 16 + e][rp0 + 2];
            acc2[0] = fma2(xa.x, wc[e], acc2[0]);
            acc2[1] = fma2(xa.y, wc[e], acc2[1]);
            acc2[2] = fma2(xb.x, wc[e], acc2[2]);
            acc2[3] = fma2(xb.y, wc[e], acc2[3]);
        }
    }
    float* dst = half ? g_Q : g_P;
    ull h2c = pack2(0.5f, 0.5f);
#pragma unroll
    for (int p = 0; p < 4; p++) {
        acc2[p] = mul2(acc2[p], h2c);
        float lo, hi; unpack2(acc2[p], lo, hi);
        int rp = rp0 + p;
        dst[(row0 + 2 * rp) * HH + k] = lo;
        dst[(row0 + 2 * rp + 1) * HH + k] = hi;
    }
}

// ---------------------------------------------------------------------------
// Kernel 2: S[b,i,k] += mj * silu(h),  h/2 = P'_i + Q'_j + dist*wd'
// silu(h) = (h/2)*(1 + tanh(h/2)), tanh evaluated on f16x2 (1 MUFU / 2 elems).
// 32x32 pair tile, 512 threads, grid (8,8,8)=512 CTAs, single prologue sync.
// ---------------------------------------------------------------------------
__global__ __launch_bounds__(512)
void k_edge(const float* __restrict__ pos,
            const float* __restrict__ mask,
            const float* __restrict__ We1) {
    __shared__ __align__(16) float qsm[TJ][HH];   // 16 KB
    __shared__ __align__(16) float bsm[TI][HH];   // 16 KB
    __shared__ ull dsm2[TI][TJ];                  // 8 KB  (dist,dist)
    __shared__ ull msm2[TJ];                      // (mj,mj)

    int js = blockIdx.x;
    int i0 = blockIdx.y * TI;
    int b  = blockIdx.z;
    int tid = threadIdx.x;
    int j0 = js * TJ;

    {
        const float4* bsrc = (const float4*)&g_P[(b * NN + i0) * HH];
        const float4* qsrc = (const float4*)&g_Q[(b * NN + j0) * HH];
#pragma unroll
        for (int q = 0; q < 2; q++) {
            ((float4*)bsm)[tid + q * 512] = bsrc[tid + q * 512];
            ((float4*)qsm)[tid + q * 512] = qsrc[tid + q * 512];
        }
    }
    if (tid < TJ) {
        float m = mask[b * NN + j0 + tid];
        msm2[tid] = pack2(m, m);
    }
#pragma unroll
    for (int t = 0; t < 2; t++) {
        int idx = tid + t * 512;
        int il = idx >> 5, jl = idx & 31;
        const float* pi = &pos[(b * NN + i0 + il) * 3];
        const float* pj = &pos[(b * NN + j0 + jl) * 3];
        float dx = pi[0] - pj[0], dy = pi[1] - pj[1], dz = pi[2] - pj[2];
        float sq = fmaf(dx, dx, fmaf(dy, dy, dz * dz));
        float d = (sq > 0.0f) ? sqrtfast(sq) : 0.0f;
        dsm2[il][jl] = pack2(d, d);
    }
    __syncthreads();

    int il = tid >> 4;            // 0..31
    int k0 = (tid & 15) * 8;

    ull base2[4], wd2[4], acc2[4];
#pragma unroll
    for (int p = 0; p < 4; p++) {
        float wlo = 0.5f * We1[2 * HH * HH + k0 + 2 * p];
        float whi = 0.5f * We1[2 * HH * HH + k0 + 2 * p + 1];
        wd2[p] = pack2(wlo, whi);
        base2[p] = ((const ull*)&bsm[il][k0])[p];
        acc2[p] = 0ULL;
    }

#pragma unroll 4
    for (int jl = 0; jl < TJ; jl++) {
        ull dist2 = dsm2[il][jl];
        ull mj2 = msm2[jl];
        ulonglong2 qa = *(const ulonglong2*)&qsm[jl][k0];
        ulonglong2 qb = *(const ulonglong2*)&qsm[jl][k0 + 4];
        ull qv[4] = {qa.x, qa.y, qb.x, qb.y};
#pragma unroll
        for (int p = 0; p < 4; p++) {
            ull h2 = fma2(dist2, wd2[p], add2(base2[p], qv[p]));  // h/2
            ull t2 = tanh2_f16(h2);
            ull s2 = fma2(h2, t2, h2);        // silu(h) = h2*(1+t)
            acc2[p] = fma2(mj2, s2, acc2[p]); // += mj * silu
        }
    }
    float* dst = &g_S[js][(b * NN + i0 + il) * HH + k0];
#pragma unroll
    for (int p = 0; p < 4; p++) {
        float lo, hi; unpack2(acc2[p], lo, hi);
        dst[2 * p] = lo;
        dst[2 * p + 1] = hi;
    }
}

// ---------------------------------------------------------------------------
// Kernel 3: agg -> node MLP -> residual.  16 rows/CTA, 512 threads,
// grid 128 = single wave. tid bits: [0:7)=k, [7:9)=row-quarter (4 rows each).
// ---------------------------------------------------------------------------
__global__ __launch_bounds__(512, 1)
void k_final(const float* __restrict__ node,
             const float* __restrict__ mask,
             const float* __restrict__ We2,
             const float* __restrict__ be2,
             const float* __restrict__ Wn1,
             const float* __restrict__ bn1,
             const float* __restrict__ Wn2,
             const float* __restrict__ bn2,
             float* __restrict__ out) {
    __shared__ __align__(16) float Ssm[16][HH];     // 8 KB
    __shared__ __align__(16) float XA[16][2 * HH];  // 16 KB  [X | A]
    __shared__ __align__(16) float Usm[16][HH];     // 8 KB
    __shared__ float msk[16];
    __shared__ float cntsh;

    int row0 = blockIdx.x * 16;
    int b = row0 >> 8;
    int tid = threadIdx.x;
    int k = tid & 127;
    int rb = (tid >> 7) * 4;

#pragma unroll
    for (int q = 0; q < 4; q++) {
        int r = rb + q;
        int g = (row0 + r) * HH + k;
        XA[r][k] = node[g];
        float s = 0.0f;
#pragma unroll
        for (int t = 0; t < NSPLIT; t++) s += g_S[t][g];
        Ssm[r][k] = s;
    }
    if (tid < 16) msk[tid] = mask[row0 + tid];
    if (tid < 32) {
        float c = 0.0f;
#pragma unroll
        for (int m = 0; m < 8; m++) c += mask[b * NN + tid * 8 + m];
#pragma unroll
        for (int o = 16; o; o >>= 1) c += __shfl_xor_sync(0xffffffffu, c, o);
        if (tid == 0) cntsh = c;
    }
    __syncthreads();
    float cnt = cntsh;

    // Stage A: agg = msk*(S@We2 + cnt*be2)/max(msk*cnt,1) -> XA[:, HH+k]
    {
        float acc[4] = {0.f, 0.f, 0.f, 0.f};
        const float* W = We2 + k;
        float w0[16], w1[16];
#pragma unroll
        for (int e = 0; e < 16; e++) w0[e] = W[e * HH];
#pragma unroll
        for (int c = 0; c < 8; c++) {
            float* wc = (c & 1) ? w1 : w0;
            float* wn = (c & 1) ? w0 : w1;
            if (c < 7) {
#pragma unroll
                for (int e = 0; e < 16; e++) wn[e] = W[((c + 1) * 16 + e) * HH];
            }
#pragma unroll
            for (int g = 0; g < 4; g++) {
#pragma unroll
                for (int q = 0; q < 4; q++) {
                    float4 s = *(const float4*)&Ssm[rb + q][c * 16 + g * 4];
                    acc[q] = fmaf(s.x, wc[g * 4 + 0], acc[q]);
                    acc[q] = fmaf(s.y, wc[g * 4 + 1], acc[q]);
                    acc[q] = fmaf(s.z, wc[g * 4 + 2], acc[q]);
                    acc[q] = fmaf(s.w, wc[g * 4 + 3], acc[q]);
                }
            }
        }
        float be2k = be2[k];
#pragma unroll
        for (int q = 0; q < 4; q++) {
            int r = rb + q;
            float denom = fmaxf(msk[r] * cnt, 1.0f);
            XA[r][HH + k] = msk[r] * (acc[q] + cnt * be2k) * (1.0f / denom);
        }
    }
    __syncthreads();

    // Stage B: u1 = silu(XA @ Wn1 + bn1)
    {
        float b1 = bn1[k];
        float acc[4] = {b1, b1, b1, b1};
        const float* W = Wn1 + k;
        float w0[16], w1[16];
#pragma unroll
        for (int e = 0; e < 16; e++) w0[e] = W[e * HH];
#pragma unroll
        for (int c = 0; c < 16; c++) {
            float* wc = (c & 1) ? w1 : w0;
            float* wn = (c & 1) ? w0 : w1;
            if (c < 15) {
#pragma unroll
                for (int e = 0; e < 16; e++) wn[e] = W[((c + 1) * 16 + e) * HH];
            }
#pragma unroll
            for (int g = 0; g < 4; g++) {
#pragma unroll
                for (int q = 0; q < 4; q++) {
                    float4 x = *(const float4*)&XA[rb + q][c * 16 + g * 4];
                    acc[q] = fmaf(x.x, wc[g * 4 + 0], acc[q]);
                    acc[q] = fmaf(x.y, wc[g * 4 + 1], acc[q]);
                    acc[q] = fmaf(x.z, wc[g * 4 + 2], acc[q]);
                    acc[q] = fmaf(x.w, wc[g * 4 + 3], acc[q]);
                }
            }
        }
#pragma unroll
        for (int q = 0; q < 4; q++) {
            float h = acc[q];
            Usm[rb + q][k] = h * fast_sigmoid(h);
        }
    }
    __syncthreads();

    // Stage C: out = node + msk * (u1 @ Wn2 + bn2)
    {
        float b2 = bn2[k];
        float acc[4] = {b2, b2, b2, b2};
        const float* W = Wn2 + k;
        float w0[16], w1[16];
#pragma unroll
        for (int e = 0; e < 16; e++) w0[e] = W[e * HH];
#pragma unroll
        for (int c = 0; c < 8; c++) {
            float* wc = (c & 1) ? w1 : w0;
            float* wn = (c & 1) ? w0 : w1;
            if (c < 7) {
#pragma unroll
                for (int e = 0; e < 16; e++) wn[e] = W[((c + 1) * 16 + e) * HH];
            }
#pragma unroll
            for (int g = 0; g < 4; g++) {
#pragma unroll
                for (int q = 0; q < 4; q++) {
                    float4 u = *(const float4*)&Usm[rb + q][c * 16 + g * 4];
                    acc[q] = fmaf(u.x, wc[g * 4 + 0], acc[q]);
                    acc[q] = fmaf(u.y, wc[g * 4 + 1], acc[q]);
                    acc[q] = fmaf(u.z, wc[g * 4 + 2], acc[q]);
                    acc[q] = fmaf(u.w, wc[g * 4 + 3], acc[q]);
                }
            }
        }
#pragma unroll
        for (int q = 0; q < 4; q++) {
            int r = rb + q;
            out[(row0 + r) * HH + k] = XA[r][k] + msk[r] * acc[q];
        }
    }
}

extern "C" void kernel_launch(void* const* d_in, const int* in_sizes, int n_in,
                              void* d_out, int out_size) {
    (void)in_sizes; (void)n_in; (void)out_size;
    const float* node = (const float*)d_in[0];
    const float* pos  = (const float*)d_in[1];
    const float* mask = (const float*)d_in[2];
    const float* We1  = (const float*)d_in[3];
    const float* be1  = (const float*)d_in[4];
    const float* We2  = (const float*)d_in[5];
    const float* be2  = (const float*)d_in[6];
    const float* Wn1  = (const float*)d_in[7];
    const float* bn1  = (const float*)d_in[8];
    const float* Wn2  = (const float*)d_in[9];
    const float* bn2  = (const float*)d_in[10];
    float* out = (float*)d_out;

    k_pq<<<ROWS / 16, 512>>>(node, We1, be1);
    k_edge<<<dim3(NSPLIT, NN / TI, BB), 512>>>(pos, mask, We1);
    k_final<<<ROWS / 16, 512>>>(node, mask, We2, be2, Wn1, bn1, Wn2, bn2, out);
}